// round 3
// baseline (speedup 1.0000x reference)
#include <cuda_runtime.h>
#include <cstdint>
#include <cstddef>

// Problem constants (fixed by the benchmark shapes)
#define N_QUERY 32768   // 1024 rays * 32 samples
#define N_LIDAR 8192
#define FDIM    128
#define THREADS 512
#define QPB     256     // queries per block
#define SPLIT   4       // lidar quarters per block
#define CHUNK   (N_LIDAR / SPLIT)   // 2048 points per thread-task
#define NBLK    (N_QUERY / QPB)     // 128 blocks
#define TILE    64      // points per guarded best-update

using u64 = unsigned long long;

// ---- packed f32x2 helpers (sm_103a): bitwise-identical to scalar rn ops ----
__device__ __forceinline__ u64 dup2(float x) {
    u64 r; asm("mov.b64 %0, {%1, %1};" : "=l"(r) : "f"(x)); return r;
}
__device__ __forceinline__ u64 mul2(u64 a, u64 b) {
    u64 d; asm("mul.rn.f32x2 %0, %1, %2;" : "=l"(d) : "l"(a), "l"(b)); return d;
}
__device__ __forceinline__ u64 fma2(u64 a, u64 b, u64 c) {
    u64 d; asm("fma.rn.f32x2 %0, %1, %2, %3;" : "=l"(d) : "l"(a), "l"(b), "l"(c)); return d;
}
__device__ __forceinline__ u64 add2(u64 a, u64 b) {
    u64 d; asm("add.rn.f32x2 %0, %1, %2;" : "=l"(d) : "l"(a), "l"(b)); return d;
}
__device__ __forceinline__ float2 asf2(u64 v) {
    float2 f; asm("mov.b64 {%0, %1}, %2;" : "=f"(f.x), "=f"(f.y) : "l"(v)); return f;
}

// d2 for a pair of lidar points, replicating the reference rounding exactly:
//   cross = fma(qz,kz, fma(qy,ky, rn(qx*kx)))          (dot accumulation order)
//   d2    = rn( rn(qsq - 2*cross) + ksq )              (fma(cross,-2,qsq) == sub form exactly)
__device__ __forceinline__ u64 pair_d2(u64 kx, u64 ky, u64 kz, u64 ks,
                                       u64 qx, u64 qy, u64 qz, u64 qs, u64 neg2) {
    u64 cross = fma2(qz, kz, fma2(qy, ky, mul2(qx, kx)));
    return add2(fma2(cross, neg2, qs), ks);
}

// 8-point group: shared LDS loads feed TWO queries; value-only min trees.
__device__ __forceinline__ void group_min8_2q(
    const float* __restrict__ skx, const float* __restrict__ sky,
    const float* __restrict__ skz, const float* __restrict__ sks, int j,
    u64 qx0, u64 qy0, u64 qz0, u64 qs0,
    u64 qx1, u64 qy1, u64 qz1, u64 qs1,
    u64 neg2, float& m0, float& m1)
{
    ulonglong2 kxa = *(const ulonglong2*)(skx + j);
    ulonglong2 kxb = *(const ulonglong2*)(skx + j + 4);
    ulonglong2 kya = *(const ulonglong2*)(sky + j);
    ulonglong2 kyb = *(const ulonglong2*)(sky + j + 4);
    ulonglong2 kza = *(const ulonglong2*)(skz + j);
    ulonglong2 kzb = *(const ulonglong2*)(skz + j + 4);
    ulonglong2 ksa = *(const ulonglong2*)(sks + j);
    ulonglong2 ksb = *(const ulonglong2*)(sks + j + 4);

    float2 a0 = asf2(pair_d2(kxa.x, kya.x, kza.x, ksa.x, qx0, qy0, qz0, qs0, neg2));
    float2 a1 = asf2(pair_d2(kxa.y, kya.y, kza.y, ksa.y, qx0, qy0, qz0, qs0, neg2));
    float2 a2 = asf2(pair_d2(kxb.x, kyb.x, kzb.x, ksb.x, qx0, qy0, qz0, qs0, neg2));
    float2 a3 = asf2(pair_d2(kxb.y, kyb.y, kzb.y, ksb.y, qx0, qy0, qz0, qs0, neg2));
    m0 = fminf(fminf(fminf(a0.x, a0.y), fminf(a1.x, a1.y)),
               fminf(fminf(a2.x, a2.y), fminf(a3.x, a3.y)));

    float2 b0 = asf2(pair_d2(kxa.x, kya.x, kza.x, ksa.x, qx1, qy1, qz1, qs1, neg2));
    float2 b1 = asf2(pair_d2(kxa.y, kya.y, kza.y, ksa.y, qx1, qy1, qz1, qs1, neg2));
    float2 b2 = asf2(pair_d2(kxb.x, kyb.x, kzb.x, ksb.x, qx1, qy1, qz1, qs1, neg2));
    float2 b3 = asf2(pair_d2(kxb.y, kyb.y, kzb.y, ksb.y, qx1, qy1, qz1, qs1, neg2));
    m1 = fminf(fminf(fminf(b0.x, b0.y), fminf(b1.x, b1.y)),
               fminf(fminf(b2.x, b2.y), fminf(b3.x, b3.y)));
}

// Exact first-index recovery in a 64-point tile (bit-identical scalar math).
__device__ __forceinline__ int recover_idx(
    const float* __restrict__ skx, const float* __restrict__ sky,
    const float* __restrict__ skz, const float* __restrict__ sks,
    int btile, float qx, float qy, float qz, float qs, float best)
{
    int bi = btile;
    bool found = false;
    #pragma unroll 4
    for (int i = 0; i < TILE; i++) {
        const int j = btile + i;
        float cross = __fmaf_rn(qz, skz[j],
                      __fmaf_rn(qy, sky[j], __fmul_rn(qx, skx[j])));
        float d2 = __fadd_rn(__fmaf_rn(cross, -2.0f, qs), sks[j]);
        if (!found && d2 == best) { bi = j; found = true; }
    }
    return bi;
}

__global__ void __launch_bounds__(THREADS, 1)
nn_gather_kernel(const float* __restrict__ pts,
                 const float* __restrict__ lidar,
                 const float* __restrict__ features,
                 float* __restrict__ out)
{
    extern __shared__ float sm[];
    float* skx = sm;
    float* sky = sm + N_LIDAR;
    float* skz = sm + 2 * N_LIDAR;
    float* sks = sm + 3 * N_LIDAR;
    float* cd2  = sm + 4 * N_LIDAR;                    // [SPLIT][QPB] candidate d2
    int*   cidx = (int*)(sm + 4 * N_LIDAR + SPLIT * QPB); // [SPLIT][QPB] candidate idx
    int*   sidx = (int*)(sm + 4 * N_LIDAR + 2 * SPLIT * QPB); // [QPB] final idx

    const int tid = threadIdx.x;

    // Cooperative SoA fill of lidar points + ||k||^2 (stepwise rounding (x^2+y^2)+z^2)
    for (int i = tid; i < N_LIDAR; i += THREADS) {
        float kx = lidar[3 * i + 0];
        float ky = lidar[3 * i + 1];
        float kz = lidar[3 * i + 2];
        skx[i] = kx; sky[i] = ky; skz[i] = kz;
        sks[i] = __fadd_rn(__fadd_rn(__fmul_rn(kx, kx), __fmul_rn(ky, ky)),
                           __fmul_rn(kz, kz));
    }
    __syncthreads();

    // Thread task: query pair (tid & 127) over lidar quarter (tid >> 7)
    const int pair = tid & 127;
    const int quarter = tid >> 7;
    const int q0 = 2 * pair;           // block-local query ids
    const int q1 = q0 + 1;
    const int m0 = blockIdx.x * QPB + q0;
    const int m1 = m0 + 1;

    const float qx0 = pts[3 * m0 + 0], qy0 = pts[3 * m0 + 1], qz0 = pts[3 * m0 + 2];
    const float qx1 = pts[3 * m1 + 0], qy1 = pts[3 * m1 + 1], qz1 = pts[3 * m1 + 2];
    const float qs0 = __fadd_rn(__fadd_rn(__fmul_rn(qx0, qx0), __fmul_rn(qy0, qy0)),
                                __fmul_rn(qz0, qz0));
    const float qs1 = __fadd_rn(__fadd_rn(__fmul_rn(qx1, qx1), __fmul_rn(qy1, qy1)),
                                __fmul_rn(qz1, qz1));

    const u64 QX0 = dup2(qx0), QY0 = dup2(qy0), QZ0 = dup2(qz0), QS0 = dup2(qs0);
    const u64 QX1 = dup2(qx1), QY1 = dup2(qy1), QZ1 = dup2(qz1), QS1 = dup2(qs1);
    const u64 NEG2 = dup2(-2.0f);

    float best0 = __int_as_float(0x7f800000), best1 = best0;
    int btile0 = quarter * CHUNK, btile1 = btile0;

    // Branch-free 64-point tiles over this thread's lidar quarter.
    const int tbeg = quarter * CHUNK;
    const int tend = tbeg + CHUNK;
    for (int t = tbeg; t < tend; t += TILE) {
        float g0[8], g1[8];
        #pragma unroll
        for (int g = 0; g < 8; g++)
            group_min8_2q(skx, sky, skz, sks, t + 8 * g,
                          QX0, QY0, QZ0, QS0, QX1, QY1, QZ1, QS1,
                          NEG2, g0[g], g1[g]);
        float tm0 = fminf(fminf(fminf(g0[0], g0[1]), fminf(g0[2], g0[3])),
                          fminf(fminf(g0[4], g0[5]), fminf(g0[6], g0[7])));
        float tm1 = fminf(fminf(fminf(g1[0], g1[1]), fminf(g1[2], g1[3])),
                          fminf(fminf(g1[4], g1[5]), fminf(g1[6], g1[7])));
        if (tm0 < best0) { best0 = tm0; btile0 = t; }  // strict < : earliest tile on ties
        if (tm1 < best1) { best1 = tm1; btile1 = t; }
    }

    // Exact first-index recovery within winning tiles (global lidar indices).
    const int bi0 = recover_idx(skx, sky, skz, sks, btile0, qx0, qy0, qz0, qs0, best0);
    const int bi1 = recover_idx(skx, sky, skz, sks, btile1, qx1, qy1, qz1, qs1, best1);

    cd2[quarter * QPB + q0] = best0;  cidx[quarter * QPB + q0] = bi0;
    cd2[quarter * QPB + q1] = best1;  cidx[quarter * QPB + q1] = bi1;
    __syncthreads();

    // Combine the 4 quarter-candidates per query (ascending quarter, strict <).
    if (tid < QPB) {
        float b = cd2[tid];
        int   i = cidx[tid];
        #pragma unroll
        for (int s = 1; s < SPLIT; s++) {
            float d = cd2[s * QPB + tid];
            int   j = cidx[s * QPB + tid];
            if (d < b) { b = d; i = j; }  // earlier quarter kept on ties (lower index)
        }
        sidx[tid] = i;
    }
    __syncthreads();

    // Warp-cooperative coalesced gather: one query row == 32 lanes x float4
    const int lane = tid & 31;
    const int warp = tid >> 5;
    const size_t qbase = (size_t)blockIdx.x * QPB;
    for (int q = warp; q < QPB; q += THREADS / 32) {
        const int src = sidx[q];
        const float4 v = *(const float4*)(features + (size_t)src * FDIM + lane * 4);
        *(float4*)(out + (qbase + q) * FDIM + lane * 4) = v;
    }
}

extern "C" void kernel_launch(void* const* d_in, const int* in_sizes, int n_in,
                              void* d_out, int out_size) {
    const float* pts      = (const float*)d_in[0];  // (1, 1024, 32, 3)
    const float* lidar    = (const float*)d_in[1];  // (1, 8192, 3)
    const float* features = (const float*)d_in[2];  // (1, 8192, 128)
    float* out = (float*)d_out;                     // (1, 1024, 32, 128)

    // 128 KB lidar SoA + combine scratch
    const int smem_bytes = (4 * N_LIDAR + 2 * SPLIT * QPB + QPB) * (int)sizeof(float);
    cudaFuncSetAttribute(nn_gather_kernel,
                         cudaFuncAttributeMaxDynamicSharedMemorySize, smem_bytes);

    nn_gather_kernel<<<NBLK, THREADS, smem_bytes>>>(pts, lidar, features, out);
}